// round 16
// baseline (speedup 1.0000x reference)
#include <cuda_runtime.h>
#include <cuda_bf16.h>

#define TSTEPS 127
#define AA_ 6

typedef unsigned long long u64;

__device__ __forceinline__ float sigm_f(float x) {
    return __fdividef(1.f, 1.f + __expf(-x));
}
__device__ __forceinline__ float tanh_f(float x) {
    float e = __expf(-2.f * fabsf(x));
    float r = __fdividef(1.f - e, 1.f + e);
    return copysignf(r, x);
}
__device__ __forceinline__ void fma2(u64& d, u64 a, u64 b) {
    asm("fma.rn.f32x2 %0, %1, %2, %0;" : "+l"(d) : "l"(a), "l"(b));
}
__device__ __forceinline__ float hsum2(u64 v) {
    unsigned lo, hi;
    asm("mov.b64 {%0,%1}, %2;" : "=r"(lo), "=r"(hi) : "l"(v));
    return __uint_as_float(lo) + __uint_as_float(hi);
}

// ---------------------------------------------------------------------------
// run_body<NR>: R8's loop layout (256 threads, 8 warps), NR rows/block.
//   t<192      : GRU dot row o=t (Whh row in 32 regs), NR batch rows.
//   t in[192,256): mlp1 dim d=t-192 (m1w row in regs), NR rows. bar.sync 1,64;
//                then warp 6 lanes < NR*6 do mlp2 (smem M2S) + argmax scan.
//   pointwise  : NR*64 tasks; task = t (+256 for t<64 when NR=5).
// ---------------------------------------------------------------------------
template<int NR>
__device__ __forceinline__ void run_body(
    const float* __restrict__ s_h, const int* __restrict__ a_h,
    const float* __restrict__ b_z,
    const float* __restrict__ w1, const float* __restrict__ b1,
    const float* __restrict__ w2, const float* __restrict__ b2,
    const float* __restrict__ fcw, const float* __restrict__ fcb,
    const float* __restrict__ emb,
    const float* __restrict__ wih, const float* __restrict__ whh,
    const float* __restrict__ bih, const float* __restrict__ bhh_g,
    const float* __restrict__ m1w, const float* __restrict__ m1b,
    const float* __restrict__ m2w, const float* __restrict__ m2b,
    float* __restrict__ out_logits, float* __restrict__ out_masks,
    int rbase, float* dyn)
{
    // carved dynamic smem (sized for NR=5 max)
    float* sw1 = dyn;                  // 2304
    float* sw2 = sw1 + 2304;           // 9216
    float* s0  = sw2 + 9216;           // 2560
    float* o1  = s0 + 2560;            // 5760
    float* o2  = o1 + 5760;            // 2560
    float* AT  = o2 + 2560;            // 1248
    float* GH  = AT + 1248;            // 960
    float* HN  = GH + 960;             // 340
    float* HID = HN + 340;             // 340
    float* XV  = HID + 340;            // 640
    float* M2S = XV + 640;             // 384
    float* LG  = M2S + 384;            // 40
    int*  ACTS = (int*)(LG + 40);      // 8

    int t = threadIdx.x;
    int w = t >> 5, lane = t & 31;

    // ================= PREAMBLE =================
    for (int i = t; i < 2304; i += 256) sw1[i] = w1[i];
    for (int i = t; i < 9216; i += 256) sw2[i] = w2[i];
    for (int i = t; i < NR * 512; i += 256) {
        int rr = i >> 9;
        s0[i] = s_h[(rbase + rr) * 65536 + (i & 511)];   // frame t=0
    }
    for (int i = t; i < NR * 128; i += 256) {
        int rr = i >> 7, tt = i & 127;
        int v = a_h[(rbase + rr) * 128 + tt];
        out_masks[(rbase + rr) * 128 + tt] = (v != (AA_ - 1)) ? 1.f : 0.f;
    }
    // FULL zero-init of replay-carried state (strided loops, all indices)
    for (int i = t; i < 5 * 68; i += 256) { HN[i] = 0.f; HID[i] = 0.f; }
    if (t < 40) LG[t] = 0.f;
    if (t < 5) ACTS[t] = AA_ - 1;
    __syncthreads();

    // conv1: tasks = rr(NR) x oc(32) x y(6)
    for (int task = t; task < NR * 192; task += 256) {
        int rr = task / 192, jj = task % 192;
        int oc = jj / 6, y = jj % 6;
        float bb = b1[oc];
        float acc0 = bb, acc1 = bb, acc2 = bb, acc3 = bb, acc4 = bb, acc5 = bb;
        const float* sin = s0 + rr * 512;
        const float* kpb = sw1 + oc * 72;
        #pragma unroll
        for (int ic = 0; ic < 8; ic++) {
            #pragma unroll
            for (int ky = 0; ky < 3; ky++) {
                const float* ip = sin + ic * 64 + (y + ky) * 8;
                const float* kp = kpb + ic * 9 + ky * 3;
                float k0 = kp[0], k1 = kp[1], k2 = kp[2];
                float i0 = ip[0], i1 = ip[1], i2 = ip[2], i3 = ip[3];
                float i4 = ip[4], i5 = ip[5], i6 = ip[6], i7 = ip[7];
                acc0 += i0 * k0 + i1 * k1 + i2 * k2;
                acc1 += i1 * k0 + i2 * k1 + i3 * k2;
                acc2 += i2 * k0 + i3 * k1 + i4 * k2;
                acc3 += i3 * k0 + i4 * k1 + i5 * k2;
                acc4 += i4 * k0 + i5 * k1 + i6 * k2;
                acc5 += i5 * k0 + i6 * k1 + i7 * k2;
            }
        }
        float* op = o1 + rr * 1152 + oc * 36 + y * 6;
        op[0] = fmaxf(acc0, 0.f); op[1] = fmaxf(acc1, 0.f);
        op[2] = fmaxf(acc2, 0.f); op[3] = fmaxf(acc3, 0.f);
        op[4] = fmaxf(acc4, 0.f); op[5] = fmaxf(acc5, 0.f);
    }
    __syncthreads();

    // conv2: tasks = rr(NR) x oc(32) x y(4)
    for (int task = t; task < NR * 128; task += 256) {
        int rr = task >> 7, jj = task & 127;
        int oc = jj >> 2, y = jj & 3;
        float bb = b2[oc];
        float acc0 = bb, acc1 = bb, acc2 = bb, acc3 = bb;
        const float* iin = o1 + rr * 1152;
        const float* kpb = sw2 + oc * 288;
        #pragma unroll 4
        for (int ic = 0; ic < 32; ic++) {
            #pragma unroll
            for (int ky = 0; ky < 3; ky++) {
                const float* ip = iin + ic * 36 + (y + ky) * 6;
                const float* kp = kpb + ic * 9 + ky * 3;
                float k0 = kp[0], k1 = kp[1], k2 = kp[2];
                float i0 = ip[0], i1 = ip[1], i2 = ip[2];
                float i3 = ip[3], i4 = ip[4], i5 = ip[5];
                acc0 += i0 * k0 + i1 * k1 + i2 * k2;
                acc1 += i1 * k0 + i2 * k1 + i3 * k2;
                acc2 += i2 * k0 + i3 * k1 + i4 * k2;
                acc3 += i3 * k0 + i4 * k1 + i5 * k2;
            }
        }
        float* op = o2 + rr * 512 + oc * 16 + y * 4;
        op[0] = fmaxf(acc0, 0.f); op[1] = fmaxf(acc1, 0.f);
        op[2] = fmaxf(acc2, 0.f); op[3] = fmaxf(acc3, 0.f);
    }
    __syncthreads();

    // fc: tasks = rr(NR) x o(64), warp-cooperative coalesced float4 -> XV
    for (int task = w; task < NR * 64; task += 8) {
        int rr = task >> 6, o = task & 63;
        const float4* wp = (const float4*)(fcw + o * 512);
        const float4* xp = (const float4*)(o2 + rr * 512);
        float acc = 0.f;
        #pragma unroll
        for (int i = 0; i < 4; i++) {
            float4 a = wp[lane + 32 * i];
            float4 b = xp[lane + 32 * i];
            acc += a.x * b.x + a.y * b.y + a.z * b.z + a.w * b.w;
        }
        #pragma unroll
        for (int d = 16; d > 0; d >>= 1)
            acc += __shfl_xor_sync(0xffffffffu, acc, d);
        if (lane == 0)
            XV[rr * 128 + o] = fmaxf(acc + fcb[o], 0.f);
    }
    // b_z half of XV — STRIDED LOOP (R15 bug: `if (t < NR*64)` left row 4
    // unwritten with 256 threads when NR=5 -> garbage base_gx for 48 rows)
    for (int i = t; i < NR * 64; i += 256) {
        int rr = i >> 6, k = i & 63;
        XV[rr * 128 + 64 + k] = b_z[((rbase + rr) / 10) * 64 + k];
    }
    for (int idx = t; idx < 6 * 192; idx += 256) {
        int a = idx / 192, o = idx % 192;
        float sum = 0.f;
        #pragma unroll
        for (int jj = 0; jj < 6; jj++) sum += emb[a * 6 + jj] * wih[o * 134 + 64 + jj];
        AT[a * 208 + o] = sum;
    }
    for (int i = t; i < 384; i += 256) M2S[i] = m2w[i];
    __syncthreads();

    // ---- pointwise constants: up to 2 tasks per thread (NR=5, t<64) ----
    float bg0[2], bg1[2], bg2[2], hreg[2];
    hreg[0] = 0.f; hreg[1] = 0.f;
    #pragma unroll
    for (int k = 0; k < 2; k++) {
        int task = t + 256 * k;
        bg0[k] = 0.f; bg1[k] = 0.f; bg2[k] = 0.f;
        if (task < NR * 64) {
            int pr = task >> 6, pd = task & 63;
            float s0v = bih[pd], s1v = bih[64 + pd], s2v = bih[128 + pd];
            const float* xv = XV + pr * 128;
            const float* w0 = wih + pd * 134;
            const float* w1r = wih + (64 + pd) * 134;
            const float* w2r = wih + (128 + pd) * 134;
            for (int kk = 0; kk < 64; kk++) {
                float x = xv[kk];
                s0v += x * w0[kk]; s1v += x * w1r[kk]; s2v += x * w2r[kk];
            }
            for (int kk = 0; kk < 64; kk++) {
                float x = xv[64 + kk];
                s0v += x * w0[70 + kk]; s1v += x * w1r[70 + kk]; s2v += x * w2r[70 + kk];
            }
            bg0[k] = s0v; bg1[k] = s1v; bg2[k] = s2v;
        }
    }

    // ---- dot-role weights into registers ----
    int m2i = t - 192;                       // warp-6 mlp2 task index
    int r2 = m2i / 6, a2 = m2i - r2 * 6;
    bool m2v = (t >= 192 && m2i < NR * 6);   // warp 6 lanes 0..NR*6-1
    ulonglong2 wq[16];
    float dbias;
    if (t < 192) {
        const ulonglong2* wp = (const ulonglong2*)(whh + t * 64);
        #pragma unroll
        for (int k = 0; k < 16; k++) wq[k] = wp[k];
        dbias = bhh_g[t];
    } else {
        const ulonglong2* wp = (const ulonglong2*)(m1w + (t - 192) * 64);
        #pragma unroll
        for (int k = 0; k < 16; k++) wq[k] = wp[k];
        dbias = m1b[t - 192];
    }
    float lb = m2v ? m2b[a2] : 0.f;

    // ================= RECURRENCE =================
    for (int i = 0; i <= TSTEPS; i++) {
        __syncthreads();   // h_new(i-1) settled

        if (t < 192) {
            if (i < TSTEPS) {
                u64 acc[NR];
                #pragma unroll
                for (int r = 0; r < NR; r++) acc[r] = 0ull;
                const ulonglong2* hq = (const ulonglong2*)HN;
                #pragma unroll
                for (int k4 = 0; k4 < 16; k4++) {
                    u64 wl = wq[k4].x, wh = wq[k4].y;
                    #pragma unroll
                    for (int r = 0; r < NR; r++) {
                        ulonglong2 x = hq[r * 17 + k4];
                        fma2(acc[r], x.x, wl); fma2(acc[r], x.y, wh);
                    }
                }
                #pragma unroll
                for (int r = 0; r < NR; r++)
                    GH[r * 192 + t] = hsum2(acc[r]) + dbias;
            }
        } else {
            if (i > 0) {
                int d = t - 192;
                u64 acc[NR];
                #pragma unroll
                for (int r = 0; r < NR; r++) acc[r] = 0ull;
                const ulonglong2* hq = (const ulonglong2*)HN;
                #pragma unroll
                for (int k4 = 0; k4 < 16; k4++) {
                    u64 wl = wq[k4].x, wh = wq[k4].y;
                    #pragma unroll
                    for (int r = 0; r < NR; r++) {
                        ulonglong2 x = hq[r * 17 + k4];
                        fma2(acc[r], x.x, wl); fma2(acc[r], x.y, wh);
                    }
                }
                #pragma unroll
                for (int r = 0; r < NR; r++)
                    HID[r * 68 + d] = tanh_f(hsum2(acc[r]) + dbias);
            }
            asm volatile("bar.sync 1, 64;" ::: "memory");  // warps 6,7
            if (i > 0) {
                if (m2v) {
                    u64 al = 0ull, bl = 0ull;
                    const ulonglong2* hh = (const ulonglong2*)(HID + r2 * 68);
                    const ulonglong2* mm = (const ulonglong2*)(M2S + a2 * 64);
                    #pragma unroll
                    for (int k4 = 0; k4 < 16; k4 += 2) {
                        ulonglong2 h0 = hh[k4], h1 = hh[k4 + 1];
                        ulonglong2 m0 = mm[k4], m1 = mm[k4 + 1];
                        fma2(al, h0.x, m0.x); fma2(al, h0.y, m0.y);
                        fma2(bl, h1.x, m1.x); fma2(bl, h1.y, m1.y);
                    }
                    float lacc = hsum2(al) + hsum2(bl) + lb;
                    out_logits[((rbase + r2) * TSTEPS + (i - 1)) * 6 + a2] = lacc;
                    LG[r2 * 8 + a2] = lacc;
                }
                __syncwarp();
                if (m2i >= 0 && m2i < NR) {   // one lane per row: first-max scan
                    const float* lg = LG + m2i * 8;
                    float bv = lg[0]; int bi = 0;
                    #pragma unroll
                    for (int a = 1; a < 6; a++) {
                        float v = lg[a];
                        if (v > bv) { bv = v; bi = a; }
                    }
                    ACTS[m2i] = bi;
                }
            }
        }
        __syncthreads();   // gh(i) + ACTS(i-1) visible

        if (i < TSTEPS) {
            #pragma unroll
            for (int k = 0; k < 2; k++) {
                int task = t + 256 * k;
                if (task < NR * 64) {
                    int pr = task >> 6, pd = task & 63;
                    float ghr = GH[pr * 192 + pd];
                    float ghz = GH[pr * 192 + 64 + pd];
                    float ghn = GH[pr * 192 + 128 + pd];
                    const float* atr = AT + ACTS[pr] * 208;
                    float rg = sigm_f(bg0[k] + atr[pd] + ghr);
                    float zg = sigm_f(bg1[k] + atr[64 + pd] + ghz);
                    float ng = tanh_f(bg2[k] + atr[128 + pd] + rg * ghn);
                    hreg[k] = (1.f - zg) * ng + zg * hreg[k];
                    HN[pr * 68 + pd] = hreg[k];
                }
            }
        }
    }
}

// 148 blocks: 0..47 -> 5 rows, 48..147 -> 4 rows (48*5 + 100*4 = 640).
__global__ void __launch_bounds__(256, 1) fused_kernel(
    const float* __restrict__ s_h, const int* __restrict__ a_h,
    const float* __restrict__ b_z,
    const float* __restrict__ w1, const float* __restrict__ b1,
    const float* __restrict__ w2, const float* __restrict__ b2,
    const float* __restrict__ fcw, const float* __restrict__ fcb,
    const float* __restrict__ emb,
    const float* __restrict__ wih, const float* __restrict__ whh,
    const float* __restrict__ bih, const float* __restrict__ bhh_g,
    const float* __restrict__ m1w, const float* __restrict__ m1b,
    const float* __restrict__ m2w, const float* __restrict__ m2b,
    float* __restrict__ out_logits, float* __restrict__ out_masks)
{
    extern __shared__ float dyn[];
    int bid = blockIdx.x;
    if (bid < 48) {
        run_body<5>(s_h, a_h, b_z, w1, b1, w2, b2, fcw, fcb, emb,
                    wih, whh, bih, bhh_g, m1w, m1b, m2w, m2b,
                    out_logits, out_masks, bid * 5, dyn);
    } else {
        run_body<4>(s_h, a_h, b_z, w1, b1, w2, b2, fcw, fcb, emb,
                    wih, whh, bih, bhh_g, m1w, m1b, m2w, m2b,
                    out_logits, out_masks, 240 + (bid - 48) * 4, dyn);
    }
}

extern "C" void kernel_launch(void* const* d_in, const int* in_sizes, int n_in,
                              void* d_out, int out_size) {
    const float* s_h = (const float*)d_in[0];
    const int*   a_h = (const int*)  d_in[1];
    const float* b_z = (const float*)d_in[2];
    const float* w1  = (const float*)d_in[3];
    const float* b1  = (const float*)d_in[4];
    const float* w2  = (const float*)d_in[5];
    const float* b2  = (const float*)d_in[6];
    const float* fcw = (const float*)d_in[7];
    const float* fcb = (const float*)d_in[8];
    const float* emb = (const float*)d_in[9];
    const float* wih = (const float*)d_in[10];
    const float* whh = (const float*)d_in[11];
    const float* bih = (const float*)d_in[12];
    const float* bhh = (const float*)d_in[13];
    const float* m1w = (const float*)d_in[14];
    const float* m1b = (const float*)d_in[15];
    const float* m2w = (const float*)d_in[16];
    const float* m2b = (const float*)d_in[17];

    float* out = (float*)d_out;
    float* out_logits = out;                         // [B,N,T-1,A]
    float* out_masks  = out + 640 * TSTEPS * AA_;    // [B,N,T,1]

    static const size_t DYN_SMEM = 26368 * sizeof(float);   // ~105.5 KB
    cudaFuncSetAttribute(fused_kernel,
                         cudaFuncAttributeMaxDynamicSharedMemorySize,
                         (int)DYN_SMEM);

    fused_kernel<<<148, 256, DYN_SMEM>>>(s_h, a_h, b_z, w1, b1, w2, b2,
                                         fcw, fcb, emb, wih, whh, bih, bhh,
                                         m1w, m1b, m2w, m2b,
                                         out_logits, out_masks);
}